// round 4
// baseline (speedup 1.0000x reference)
#include <cuda_runtime.h>
#include <cstdint>

// C4TransformerVM: exact 4-byte ripple-carry add over one-hot byte encodings.
// softmax(temp=100) over integer logit gaps >=1 scaled by 100 makes every
// intermediate one-hot to ~exp(-100) ~ 3.6e-44 in fp32 -> decode (argmax),
// uint32 add (final carry discarded per reference), re-encode one-hot.
//
// Round-3 evidence: fused kernel hit only 69% DRAM (5.6 TB/s) because each
// warp serializes load-phase -> REDUX chain -> store-phase. Split into two
// unidirectional streams:
//   decode: 256 MB pure read  -> S[N] uint32 (128 KB scratch)
//   encode: 128 MB pure write <- S[N] (L2-resident)

#define MAX_N 32768
__device__ uint32_t g_sum[MAX_N];

// ---------------------------------------------------------------------------
// Kernel 1: decode a,b -> S = A + B. One warp per n.
// Per lane: pack the found index of byte i into bits [8i, 8i+8). At most one
// lane is nonzero per byte (index 0 => all lanes 0, which is also correct),
// so a single __reduce_or_sync reconstructs the full 32-bit word.
// ---------------------------------------------------------------------------
__device__ __forceinline__ uint32_t scan8_mask(float4 v0, float4 v1, int base, int sh) {
    uint32_t idx = 0;
    if (v0.x > 0.5f) idx = (uint32_t)(base + 0);
    if (v0.y > 0.5f) idx = (uint32_t)(base + 1);
    if (v0.z > 0.5f) idx = (uint32_t)(base + 2);
    if (v0.w > 0.5f) idx = (uint32_t)(base + 3);
    if (v1.x > 0.5f) idx = (uint32_t)(base + 4);
    if (v1.y > 0.5f) idx = (uint32_t)(base + 5);
    if (v1.z > 0.5f) idx = (uint32_t)(base + 6);
    if (v1.w > 0.5f) idx = (uint32_t)(base + 7);
    return idx << sh;
}

__global__ __launch_bounds__(256) void decode_kernel(
    const float* __restrict__ a,
    const float* __restrict__ b,
    int N)
{
    const int warp_id = (blockIdx.x * blockDim.x + threadIdx.x) >> 5;
    const int lane = threadIdx.x & 31;
    if (warp_id >= N) return;
    const size_t n = (size_t)warp_id;

    // 16 float4 streaming loads, all issued before consumption (MLP ~ 16).
    float4 va[8], vb[8];
#pragma unroll
    for (int i = 0; i < 4; i++) {
        const float4* ra = reinterpret_cast<const float4*>(a + ((size_t)i * N + n) * 256);
        const float4* rb = reinterpret_cast<const float4*>(b + ((size_t)i * N + n) * 256);
        va[2 * i]     = __ldcs(ra + lane * 2);
        va[2 * i + 1] = __ldcs(ra + lane * 2 + 1);
        vb[2 * i]     = __ldcs(rb + lane * 2);
        vb[2 * i + 1] = __ldcs(rb + lane * 2 + 1);
    }

    const int base = lane * 8;
    uint32_t Ap = 0, Bp = 0;
#pragma unroll
    for (int i = 0; i < 4; i++) {
        Ap |= scan8_mask(va[2 * i], va[2 * i + 1], base, 8 * i);
        Bp |= scan8_mask(vb[2 * i], vb[2 * i + 1], base, 8 * i);
    }
    const uint32_t A = __reduce_or_sync(0xffffffffu, Ap);
    const uint32_t B = __reduce_or_sync(0xffffffffu, Bp);

    if (lane == 0) g_sum[n] = A + B;   // carry out of byte 3 discarded
}

// ---------------------------------------------------------------------------
// Kernel 2: encode S -> one-hot output. One warp per output row (4N rows),
// consecutive warps -> consecutive n within a byte-stream i (fully coalesced).
// ---------------------------------------------------------------------------
__global__ __launch_bounds__(256) void encode_kernel(
    float* __restrict__ out,
    int N)
{
    const int warp_id = (blockIdx.x * blockDim.x + threadIdx.x) >> 5;
    const int lane = threadIdx.x & 31;
    if (warp_id >= 4 * N) return;

    const int n = warp_id % N;       // row within stream
    const int i = warp_id / N;       // byte index / output stream

    const uint32_t S = g_sum[n];     // warp-uniform broadcast load (L2-hot)
    const int r = (int)((S >> (8 * i)) & 255u);

    const int base = lane * 8;
    float4 w0, w1;
    w0.x = (base + 0 == r) ? 1.0f : 0.0f;
    w0.y = (base + 1 == r) ? 1.0f : 0.0f;
    w0.z = (base + 2 == r) ? 1.0f : 0.0f;
    w0.w = (base + 3 == r) ? 1.0f : 0.0f;
    w1.x = (base + 4 == r) ? 1.0f : 0.0f;
    w1.y = (base + 5 == r) ? 1.0f : 0.0f;
    w1.z = (base + 6 == r) ? 1.0f : 0.0f;
    w1.w = (base + 7 == r) ? 1.0f : 0.0f;

    float4* ro = reinterpret_cast<float4*>(out + ((size_t)i * N + n) * 256);
    __stcs(ro + lane * 2,     w0);
    __stcs(ro + lane * 2 + 1, w1);
}

extern "C" void kernel_launch(void* const* d_in, const int* in_sizes, int n_in,
                              void* d_out, int out_size) {
    const float* a = (const float*)d_in[0];   // [4, N, 256] one-hot
    const float* b = (const float*)d_in[1];   // [4, N, 256] one-hot
    float* out = (float*)d_out;               // [4, N, 256]
    const int N = in_sizes[0] / (4 * 256);

    const int threads = 256;                  // 8 warps/block
    const int dec_blocks = (N * 32 + threads - 1) / threads;
    const int enc_blocks = (4 * N * 32 + threads - 1) / threads;

    decode_kernel<<<dec_blocks, threads>>>(a, b, N);
    encode_kernel<<<enc_blocks, threads>>>(out, N);
}

// round 5
// speedup vs baseline: 1.4124x; 1.4124x over previous
#include <cuda_runtime.h>
#include <cstdint>

// C4TransformerVM: exact 4-byte ripple-carry add over one-hot byte encodings.
// softmax(temp=100) over integer logit gaps >=1 (scaled by 100) makes every
// intermediate one-hot to ~exp(-100) ~ 3.6e-44 in fp32 -> decode (argmax),
// uint32 add (final carry discarded per reference), re-encode one-hot.
//
// R3 (fused, 67.6us): DRAM 69%, regs=40 -> loads consumed in batches, MLP~6.
// R4 (split kernels): regression — pure-write stream ran at 25% DRAM; fused
// read+write is the right shape.
// R5: fused again, but (a) launch_bounds(256,3) so ~85 regs keep all 16
// LDG.128 in flight (MLP=16), (b) 2x reduce_or instead of 8x reduce_max.

__device__ __forceinline__ uint32_t scan8_mask(float4 v0, float4 v1, int base, int sh) {
    uint32_t idx = 0;
    if (v0.x > 0.5f) idx = (uint32_t)(base + 0);
    if (v0.y > 0.5f) idx = (uint32_t)(base + 1);
    if (v0.z > 0.5f) idx = (uint32_t)(base + 2);
    if (v0.w > 0.5f) idx = (uint32_t)(base + 3);
    if (v1.x > 0.5f) idx = (uint32_t)(base + 4);
    if (v1.y > 0.5f) idx = (uint32_t)(base + 5);
    if (v1.z > 0.5f) idx = (uint32_t)(base + 6);
    if (v1.w > 0.5f) idx = (uint32_t)(base + 7);
    return idx << sh;
}

__global__ __launch_bounds__(256, 3) void neural_alu_add_kernel(
    const float* __restrict__ a,
    const float* __restrict__ b,
    float* __restrict__ out,
    int N)
{
    const int warp_id = (blockIdx.x * blockDim.x + threadIdx.x) >> 5;
    const int lane = threadIdx.x & 31;
    if (warp_id >= N) return;
    const size_t n = (size_t)warp_id;

    // ---- Load: 8 rows x 256 floats; each lane grabs 8 contiguous floats.
    // With 3 blocks/SM the compiler has ~85 regs/thread: all 16 float4 loads
    // can be live simultaneously -> MLP ~ 16.
    float4 va[8], vb[8];
#pragma unroll
    for (int i = 0; i < 4; i++) {
        const float4* ra = reinterpret_cast<const float4*>(a + ((size_t)i * N + n) * 256);
        const float4* rb = reinterpret_cast<const float4*>(b + ((size_t)i * N + n) * 256);
        va[2 * i]     = __ldcs(ra + lane * 2);
        va[2 * i + 1] = __ldcs(ra + lane * 2 + 1);
        vb[2 * i]     = __ldcs(rb + lane * 2);
        vb[2 * i + 1] = __ldcs(rb + lane * 2 + 1);
    }

    // ---- Decode: pack byte-i index into bits [8i,8i+8). At most one lane is
    // nonzero per byte (hot index 0 => all-zero, also correct), so a single
    // OR-reduction per operand reconstructs the full 32-bit word.
    const int base = lane * 8;
    uint32_t Ap = 0, Bp = 0;
#pragma unroll
    for (int i = 0; i < 4; i++) {
        Ap |= scan8_mask(va[2 * i], va[2 * i + 1], base, 8 * i);
        Bp |= scan8_mask(vb[2 * i], vb[2 * i + 1], base, 8 * i);
    }
    const uint32_t A = __reduce_or_sync(0xffffffffu, Ap);
    const uint32_t B = __reduce_or_sync(0xffffffffu, Bp);

    const uint32_t S = A + B;   // carry out of byte 3 discarded

    // ---- Encode: 4 rows x 256 floats, 8 floats/lane, branch-free.
#pragma unroll
    for (int i = 0; i < 4; i++) {
        const int r = (int)((S >> (8 * i)) & 255u);
        float4 w0, w1;
        w0.x = (base + 0 == r) ? 1.0f : 0.0f;
        w0.y = (base + 1 == r) ? 1.0f : 0.0f;
        w0.z = (base + 2 == r) ? 1.0f : 0.0f;
        w0.w = (base + 3 == r) ? 1.0f : 0.0f;
        w1.x = (base + 4 == r) ? 1.0f : 0.0f;
        w1.y = (base + 5 == r) ? 1.0f : 0.0f;
        w1.z = (base + 6 == r) ? 1.0f : 0.0f;
        w1.w = (base + 7 == r) ? 1.0f : 0.0f;
        float4* ro = reinterpret_cast<float4*>(out + ((size_t)i * N + n) * 256);
        __stcs(ro + lane * 2,     w0);
        __stcs(ro + lane * 2 + 1, w1);
    }
}

extern "C" void kernel_launch(void* const* d_in, const int* in_sizes, int n_in,
                              void* d_out, int out_size) {
    const float* a = (const float*)d_in[0];   // [4, N, 256] one-hot
    const float* b = (const float*)d_in[1];   // [4, N, 256] one-hot
    float* out = (float*)d_out;               // [4, N, 256]
    const int N = in_sizes[0] / (4 * 256);

    const int threads = 256;                  // 8 warps/block, 1 warp per n
    const int blocks = (N * 32 + threads - 1) / threads;
    neural_alu_add_kernel<<<blocks, threads>>>(a, b, out, N);
}

// round 6
// speedup vs baseline: 1.4181x; 1.0040x over previous
#include <cuda_runtime.h>
#include <cstdint>

// C4TransformerVM: exact 4-byte ripple-carry add over one-hot byte encodings.
// softmax(temp=100) over integer logit gaps (scaled by 100) makes every
// intermediate one-hot to ~exp(-100) ~ 3.6e-44 in fp32 -> decode (argmax),
// uint32 add (final carry discarded per reference), re-encode one-hot.
//
// R3 fused 67.6us @ DRAM 69% (regs=40, MLP~6).
// R4 split kernels: regression (pure-write stream only 25% DRAM).
// R5 fused + launch_bounds(256,3): 63.8us @ DRAM 77.6% (MLP=16 confirmed).
// R6: break the load->store dependency. 255/256 of the output is zeros and
// data-independent: store zeros immediately after issuing the loads (they
// drain while loads are in flight), then patch the single 1.0 per row from
// the owning lane (same thread + same address as its zero store -> program
// order guarantees the patch lands last). ~1% extra write traffic.

__device__ __forceinline__ uint32_t scan8_mask(float4 v0, float4 v1, int base, int sh) {
    uint32_t idx = 0;
    if (v0.x > 0.5f) idx = (uint32_t)(base + 0);
    if (v0.y > 0.5f) idx = (uint32_t)(base + 1);
    if (v0.z > 0.5f) idx = (uint32_t)(base + 2);
    if (v0.w > 0.5f) idx = (uint32_t)(base + 3);
    if (v1.x > 0.5f) idx = (uint32_t)(base + 4);
    if (v1.y > 0.5f) idx = (uint32_t)(base + 5);
    if (v1.z > 0.5f) idx = (uint32_t)(base + 6);
    if (v1.w > 0.5f) idx = (uint32_t)(base + 7);
    return idx << sh;
}

__global__ __launch_bounds__(256, 3) void neural_alu_add_kernel(
    const float* __restrict__ a,
    const float* __restrict__ b,
    float* __restrict__ out,
    int N)
{
    const int warp_id = (blockIdx.x * blockDim.x + threadIdx.x) >> 5;
    const int lane = threadIdx.x & 31;
    if (warp_id >= N) return;
    const size_t n = (size_t)warp_id;

    // ---- Phase 1: issue all 16 float4 loads (MLP = 16).
    float4 va[8], vb[8];
#pragma unroll
    for (int i = 0; i < 4; i++) {
        const float4* ra = reinterpret_cast<const float4*>(a + ((size_t)i * N + n) * 256);
        const float4* rb = reinterpret_cast<const float4*>(b + ((size_t)i * N + n) * 256);
        va[2 * i]     = __ldcs(ra + lane * 2);
        va[2 * i + 1] = __ldcs(ra + lane * 2 + 1);
        vb[2 * i]     = __ldcs(rb + lane * 2);
        vb[2 * i + 1] = __ldcs(rb + lane * 2 + 1);
    }

    // ---- Phase 2: store zeros to all 4 output rows. No dependency on the
    // loads -> these drain while the reads are still in flight.
    const float4 z = make_float4(0.f, 0.f, 0.f, 0.f);
#pragma unroll
    for (int i = 0; i < 4; i++) {
        float4* ro = reinterpret_cast<float4*>(out + ((size_t)i * N + n) * 256);
        __stcs(ro + lane * 2,     z);
        __stcs(ro + lane * 2 + 1, z);
    }

    // ---- Phase 3: decode. Pack byte-i index into bits [8i,8i+8); at most
    // one lane nonzero per byte (hot index 0 => all-zero, also correct), so
    // one OR-reduction per operand reconstructs the 32-bit word.
    const int base = lane * 8;
    uint32_t Ap = 0, Bp = 0;
#pragma unroll
    for (int i = 0; i < 4; i++) {
        Ap |= scan8_mask(va[2 * i], va[2 * i + 1], base, 8 * i);
        Bp |= scan8_mask(vb[2 * i], vb[2 * i + 1], base, 8 * i);
    }
    const uint32_t A = __reduce_or_sync(0xffffffffu, Ap);
    const uint32_t B = __reduce_or_sync(0xffffffffu, Bp);

    const uint32_t S = A + B;   // carry out of byte 3 discarded

    // ---- Phase 4: patch the hot element of each row. The owning lane also
    // wrote the zeros for this segment, so same-thread same-address program
    // order makes the 1.0 land last.
#pragma unroll
    for (int i = 0; i < 4; i++) {
        const int r = (int)((S >> (8 * i)) & 255u);
        if ((r >> 3) == lane) {
            __stcs(out + ((size_t)i * N + n) * 256 + r, 1.0f);
        }
    }
}

extern "C" void kernel_launch(void* const* d_in, const int* in_sizes, int n_in,
                              void* d_out, int out_size) {
    const float* a = (const float*)d_in[0];   // [4, N, 256] one-hot
    const float* b = (const float*)d_in[1];   // [4, N, 256] one-hot
    float* out = (float*)d_out;               // [4, N, 256]
    const int N = in_sizes[0] / (4 * 256);

    const int threads = 256;                  // 8 warps/block, 1 warp per n
    const int blocks = (N * 32 + threads - 1) / threads;
    neural_alu_add_kernel<<<blocks, threads>>>(a, b, out, N);
}